// round 2
// baseline (speedup 1.0000x reference)
#include <cuda_runtime.h>
#include <math.h>

#define NN 1024
#define DD 64
#define MIN_NORM 1e-15f
#define PROJ_EPS 4e-3f

// Per-row precomputed scalars (allocation-free scratch)
__device__ float g_y2[NN];     // |x_i|^2
__device__ float g_left[NN];   // x_tan_i . W[:D] + b
__device__ float g_right[NN];  // x_tan_i . W[D:]

__device__ __forceinline__ float warp_sum(float v) {
#pragma unroll
    for (int o = 16; o > 0; o >>= 1) v += __shfl_xor_sync(0xffffffffu, v, o);
    return v;
}

__device__ __forceinline__ float artanh_clip(float z) {
    z = fminf(z, 1.0f - 1e-7f);
    z = fmaxf(z, -1.0f + 1e-7f);
    return 0.5f * logf((1.0f + z) / (1.0f - z));
}

__global__ void hyp_precompute(const float* __restrict__ x,
                               const float* __restrict__ W,
                               const float* __restrict__ b) {
    int warp = (blockIdx.x * blockDim.x + threadIdx.x) >> 5;
    int lane = threadIdx.x & 31;
    if (warp >= NN) return;
    float p0 = x[warp * DD + lane];
    float p1 = x[warp * DD + lane + 32];
    float x2 = warp_sum(p0 * p0 + p1 * p1);
    float pn = fmaxf(sqrtf(x2), MIN_NORM);
    float tc = artanh_clip(pn) / pn;          // logmap0 scale (sqrt_c = 1)
    float t0 = tc * p0, t1 = tc * p1;
    float left  = warp_sum(t0 * W[lane]      + t1 * W[lane + 32]);
    float right = warp_sum(t0 * W[DD + lane] + t1 * W[DD + lane + 32]);
    if (lane == 0) {
        g_y2[warp]    = x2;
        g_left[warp]  = left + b[0];
        g_right[warp] = right;
    }
}

__global__ void hyp_agg(const float* __restrict__ x,
                        const float* __restrict__ adj,
                        float* __restrict__ out) {
    int i = (blockIdx.x * blockDim.x + threadIdx.x) >> 5;
    int lane = threadIdx.x & 31;
    if (i >= NN) return;

    float p0 = x[i * DD + lane];
    float p1 = x[i * DD + lane + 32];
    float x2i     = g_y2[i];
    float lefti   = g_left[i];
    float one_mx2 = 1.0f - x2i;                 // (1 - c*x2_i)
    float two_over_lam = fmaxf(one_mx2, MIN_NORM);  // 2/(sqrt_c*lambda_{x_i})

    float acc0 = 0.0f, acc1 = 0.0f;
    const float* adjrow = adj + (size_t)i * NN;

    for (int base = 0; base < NN; base += 32) {
        float a = adjrow[base + lane];
        unsigned mask = __ballot_sync(0xffffffffu, a != 0.0f);
        while (mask) {
            int bit = __ffs(mask) - 1;
            mask &= mask - 1;
            int j = base + bit;
            float aj = __shfl_sync(0xffffffffu, a, bit);

            float q0 = x[j * DD + lane];
            float q1 = x[j * DD + lane + 32];
            float dij = warp_sum(p0 * q0 + p1 * q1);   // p_i . p_j
            float y2j = g_y2[j];

            // mobius_add(-p_i, p_j):  xy = -dij
            float A   = 1.0f - 2.0f * dij + y2j;        // 1 + 2c*xy + c*y2
            float den = 1.0f - 2.0f * dij + x2i * y2j;
            float inv_den = 1.0f / fmaxf(den, MIN_NORM);
            float sub0 = (one_mx2 * q0 - A * p0) * inv_den;
            float sub1 = (one_mx2 * q1 - A * p1) * inv_den;

            float sn2 = warp_sum(sub0 * sub0 + sub1 * sub1);
            float sn = fmaxf(sqrtf(sn2), MIN_NORM);
            float coef = two_over_lam * artanh_clip(sn) / sn;

            float w  = aj / (1.0f + __expf(-(lefti + g_right[j])));
            float cw = w * coef;
            acc0 = fmaf(cw, sub0, acc0);
            acc1 = fmaf(cw, sub1, acc1);
        }
    }

    // ---- epilogue: reference does _expmap(u = x_i, p = support_t) ----
    // support_t = acc, point of expansion is ACC, tangent vector is X_I.
    float s2 = warp_sum(acc0 * acc0 + acc1 * acc1);   // |support|^2
    float un = fmaxf(sqrtf(x2i), MIN_NORM);            // |u| = |x_i|
    float tol = fmaxf(1.0f - s2, MIN_NORM);            // 2/lambda at p=support
    float sc = tanhf(un / tol) / un;
    float s0 = sc * p0, s1 = sc * p1;                  // "second"
    float y2 = sc * sc * x2i;                          // |second|^2

    // mobius_add(support, second)
    float xy = warp_sum(acc0 * s0 + acc1 * s1);
    float numc = 1.0f + 2.0f * xy + y2;
    float den  = fmaxf(1.0f + 2.0f * xy + s2 * y2, MIN_NORM);
    float inv_den = 1.0f / den;
    float r0 = (numc * acc0 + (1.0f - s2) * s0) * inv_den;
    float r1 = (numc * acc1 + (1.0f - s2) * s1) * inv_den;

    // proj
    float n = fmaxf(sqrtf(warp_sum(r0 * r0 + r1 * r1)), MIN_NORM);
    float maxnorm = 1.0f - PROJ_EPS;   // sqrt_c = 1
    if (n > maxnorm) {
        float s = maxnorm / n;
        r0 *= s; r1 *= s;
    }
    out[i * DD + lane]      = r0;
    out[i * DD + lane + 32] = r1;
}

extern "C" void kernel_launch(void* const* d_in, const int* in_sizes, int n_in,
                              void* d_out, int out_size) {
    // Map inputs by element count to be robust to ordering:
    //   x: NN*DD = 65536, adj: NN*NN = 1048576, att_W: 2*DD = 128, att_b: 1
    const float* x = nullptr; const float* adj = nullptr;
    const float* att_W = nullptr; const float* att_b = nullptr;
    for (int k = 0; k < n_in; k++) {
        int sz = in_sizes[k];
        if (sz == NN * NN)      adj   = (const float*)d_in[k];
        else if (sz == NN * DD) x     = (const float*)d_in[k];
        else if (sz == 2 * DD)  att_W = (const float*)d_in[k];
        else if (sz == 1)       att_b = (const float*)d_in[k];
    }
    float* out = (float*)d_out;

    // 1 warp per row; 256-thread blocks -> 8 rows/block -> 128 blocks
    hyp_precompute<<<128, 256>>>(x, att_W, att_b);
    hyp_agg<<<128, 256>>>(x, adj, out);
}

// round 3
// speedup vs baseline: 2.3772x; 2.3772x over previous
#include <cuda_runtime.h>
#include <math.h>

#define NN 1024
#define DD 64
#define MIN_NORM 1e-15f
#define PROJ_EPS 4e-3f
#define MAXDEG 96
#define WPB 8   // warps per block

__device__ float g_y2[NN];     // |x_i|^2
__device__ float g_left[NN];   // x_tan_i . W[:D] + b
__device__ float g_right[NN];  // x_tan_i . W[D:]

__device__ __forceinline__ float warp_sum(float v) {
#pragma unroll
    for (int o = 16; o > 0; o >>= 1) v += __shfl_xor_sync(0xffffffffu, v, o);
    return v;
}

__device__ __forceinline__ float artanh_clip(float z) {
    z = fminf(z, 1.0f - 1e-7f);
    z = fmaxf(z, -1.0f + 1e-7f);
    return 0.5f * __logf((1.0f + z) / (1.0f - z));
}

__global__ void hyp_precompute(const float* __restrict__ x,
                               const float* __restrict__ W,
                               const float* __restrict__ b) {
    int warp = (blockIdx.x * blockDim.x + threadIdx.x) >> 5;
    int lane = threadIdx.x & 31;
    if (warp >= NN) return;
    float p0 = x[warp * DD + lane];
    float p1 = x[warp * DD + lane + 32];
    float x2 = warp_sum(p0 * p0 + p1 * p1);
    float pn = fmaxf(sqrtf(x2), MIN_NORM);
    float z = fminf(pn, 1.0f - 1e-7f);
    float tc = 0.5f * logf((1.0f + z) / (1.0f - z)) / pn;   // logmap0 scale
    float t0 = tc * p0, t1 = tc * p1;
    float left  = warp_sum(t0 * W[lane]      + t1 * W[lane + 32]);
    float right = warp_sum(t0 * W[DD + lane] + t1 * W[DD + lane + 32]);
    if (lane == 0) {
        g_y2[warp]    = x2;
        g_left[warp]  = left + b[0];
        g_right[warp] = right;
    }
}

__global__ void __launch_bounds__(WPB * 32) hyp_agg(
        const float* __restrict__ x,
        const float* __restrict__ adj,
        float* __restrict__ out) {
    __shared__ float4 sh_p[WPB][DD / 4];
    __shared__ int    sh_j[WPB][MAXDEG];
    __shared__ float  sh_w[WPB][MAXDEG];   // adj value, then reused as alpha
    int w = threadIdx.x >> 5;
    int i = blockIdx.x * WPB + w;
    int lane = threadIdx.x & 31;
    if (i >= NN) return;

    float p0 = x[i * DD + lane];
    float p1 = x[i * DD + lane + 32];
    // stage p_i into shared (as float4-aligned rows)
    ((float*)sh_p[w])[lane]      = p0;
    ((float*)sh_p[w])[lane + 32] = p1;

    float x2i     = g_y2[i];
    float lefti   = g_left[i];
    float B       = 1.0f - x2i;                     // (1 - c*|p|^2)
    float two_over_lam = fmaxf(B, MIN_NORM);

    // ---- scan adjacency row into compact neighbor list ----
    const float* adjrow = adj + (size_t)i * NN;
    int cnt = 0;
#pragma unroll 4
    for (int base = 0; base < NN; base += 32) {
        float a = adjrow[base + lane];
        unsigned mask = __ballot_sync(0xffffffffu, a != 0.0f);
        if (a != 0.0f) {
            int pos = cnt + __popc(mask & ((1u << lane) - 1u));
            if (pos < MAXDEG) { sh_j[w][pos] = base + lane; sh_w[w][pos] = a; }
        }
        cnt += __popc(mask);
    }
    if (cnt > MAXDEG) cnt = MAXDEG;
    __syncwarp();

    // ---- phase A: one neighbor per lane, all-scalar pair math ----
    float beta_part = 0.0f;
    for (int k = lane; k < cnt; k += 32) {
        int j = sh_j[w][k];
        float aj = sh_w[w][k];
        const float4* q4 = (const float4*)(x + (size_t)j * DD);
        float d = 0.0f;
#pragma unroll
        for (int t = 0; t < DD / 4; t++) {
            float4 pq = sh_p[w][t];
            float4 qq = q4[t];
            d = fmaf(pq.x, qq.x, d); d = fmaf(pq.y, qq.y, d);
            d = fmaf(pq.z, qq.z, d); d = fmaf(pq.w, qq.w, d);
        }
        float y2j = g_y2[j];
        float A   = 1.0f - 2.0f * d + y2j;
        float den = 1.0f - 2.0f * d + x2i * y2j;
        float inv_den = 1.0f / fmaxf(den, MIN_NORM);
        // |num|^2 = A^2 |p|^2 - 2AB d + B^2 |q|^2   (all scalar)
        float num2 = fmaxf(A * A * x2i - 2.0f * A * B * d + B * B * y2j, 0.0f);
        float sn = fmaxf(sqrtf(num2) * inv_den, MIN_NORM);
        float coef = two_over_lam * artanh_clip(sn) / sn;
        float wgt  = aj / (1.0f + __expf(-(lefti + g_right[j])));
        float alpha = wgt * coef * inv_den;
        sh_w[w][k] = alpha;
        beta_part = fmaf(alpha, A, beta_part);
    }
    float beta = warp_sum(beta_part);
    __syncwarp();

    // ---- phase B: acc = B * sum(alpha_j q_j) - beta * p ----
    float acc0 = 0.0f, acc1 = 0.0f;
    for (int k = 0; k < cnt; k++) {
        float al = sh_w[w][k];
        const float* q = x + (size_t)sh_j[w][k] * DD;
        acc0 = fmaf(al, q[lane],      acc0);
        acc1 = fmaf(al, q[lane + 32], acc1);
    }
    acc0 = B * acc0 - beta * p0;
    acc1 = B * acc1 - beta * p1;

    // ---- epilogue: reference does _expmap(u = x_i, p = support_t) ----
    float s2 = warp_sum(acc0 * acc0 + acc1 * acc1);   // |support|^2
    float un = fmaxf(sqrtf(x2i), MIN_NORM);           // |u| = |x_i|
    float tol = fmaxf(1.0f - s2, MIN_NORM);
    float sc = tanhf(un / tol) / un;
    float s0 = sc * p0, s1 = sc * p1;                 // "second"
    float y2 = sc * sc * x2i;

    float xy = warp_sum(acc0 * s0 + acc1 * s1);
    float numc = 1.0f + 2.0f * xy + y2;
    float den  = fmaxf(1.0f + 2.0f * xy + s2 * y2, MIN_NORM);
    float inv_den = 1.0f / den;
    float r0 = (numc * acc0 + (1.0f - s2) * s0) * inv_den;
    float r1 = (numc * acc1 + (1.0f - s2) * s1) * inv_den;

    float n = fmaxf(sqrtf(warp_sum(r0 * r0 + r1 * r1)), MIN_NORM);
    float maxnorm = 1.0f - PROJ_EPS;
    if (n > maxnorm) {
        float s = maxnorm / n;
        r0 *= s; r1 *= s;
    }
    out[i * DD + lane]      = r0;
    out[i * DD + lane + 32] = r1;
}

extern "C" void kernel_launch(void* const* d_in, const int* in_sizes, int n_in,
                              void* d_out, int out_size) {
    const float* x = nullptr; const float* adj = nullptr;
    const float* att_W = nullptr; const float* att_b = nullptr;
    for (int k = 0; k < n_in; k++) {
        int sz = in_sizes[k];
        if (sz == NN * NN)      adj   = (const float*)d_in[k];
        else if (sz == NN * DD) x     = (const float*)d_in[k];
        else if (sz == 2 * DD)  att_W = (const float*)d_in[k];
        else if (sz == 1)       att_b = (const float*)d_in[k];
    }
    float* out = (float*)d_out;

    hyp_precompute<<<NN / 8, 256>>>(x, att_W, att_b);
    hyp_agg<<<NN / WPB, WPB * 32>>>(x, adj, out);
}

// round 4
// speedup vs baseline: 3.2827x; 1.3810x over previous
#include <cuda_runtime.h>
#include <math.h>

#define NN 1024
#define DD 64
#define MIN_NORM 1e-15f
#define PROJ_EPS 4e-3f
#define MAXDEG 96
#define WPB 8   // warps per block

__device__ __forceinline__ float warp_sum(float v) {
#pragma unroll
    for (int o = 16; o > 0; o >>= 1) v += __shfl_xor_sync(0xffffffffu, v, o);
    return v;
}

__device__ __forceinline__ float artanh_clip(float z) {
    z = fminf(z, 1.0f - 1e-7f);
    z = fmaxf(z, -1.0f + 1e-7f);
    return 0.5f * __logf((1.0f + z) / (1.0f - z));
}

__global__ void __launch_bounds__(WPB * 32) hyp_all(
        const float* __restrict__ x,
        const float* __restrict__ adj,
        const float* __restrict__ W,
        const float* __restrict__ b,
        float* __restrict__ out) {
    __shared__ float4 sh_p[WPB][DD / 4];
    __shared__ int    sh_j[WPB][MAXDEG];
    __shared__ float  sh_a[WPB][MAXDEG];   // adj value, then reused as alpha
    __shared__ float4 sh_Wr[DD / 4];       // W[D:], the "right" half

    int w = threadIdx.x >> 5;
    int i = blockIdx.x * WPB + w;
    int lane = threadIdx.x & 31;

    // ---- prefetch entire adj row: 8 independent float4 loads per lane ----
    const float4* arow = (const float4*)(adj + (size_t)i * NN);
    float4 av[8];
#pragma unroll
    for (int t = 0; t < 8; t++) av[t] = arow[t * 32 + lane];

    // stage W_right into shared (once per block)
    if (threadIdx.x < DD) ((float*)sh_Wr)[threadIdx.x] = W[DD + threadIdx.x];

    // ---- own-row scalars (overlaps the adj loads in flight) ----
    float p0 = x[i * DD + lane];
    float p1 = x[i * DD + lane + 32];
    ((float*)sh_p[w])[lane]      = p0;
    ((float*)sh_p[w])[lane + 32] = p1;

    float x2i = warp_sum(p0 * p0 + p1 * p1);
    float pn  = fmaxf(sqrtf(x2i), MIN_NORM);
    float tci = artanh_clip(pn) / pn;                    // logmap0 scale
    float lefti = warp_sum(tci * (p0 * W[lane] + p1 * W[lane + 32])) + b[0];

    float B = 1.0f - x2i;                                // (1 - c*|p_i|^2)
    float two_over_lam = fmaxf(B, MIN_NORM);

    __syncthreads();   // sh_Wr + sh_p visible

    // ---- compaction from registers: per-lane mask + one prefix scan ----
    unsigned m = 0u;
#pragma unroll
    for (int t = 0; t < 8; t++) {
        if (av[t].x != 0.0f) m |= 1u << (t * 4 + 0);
        if (av[t].y != 0.0f) m |= 1u << (t * 4 + 1);
        if (av[t].z != 0.0f) m |= 1u << (t * 4 + 2);
        if (av[t].w != 0.0f) m |= 1u << (t * 4 + 3);
    }
    int nl = __popc(m);
    int v = nl;
#pragma unroll
    for (int o = 1; o < 32; o <<= 1) {
        int u = __shfl_up_sync(0xffffffffu, v, o);
        if (lane >= o) v += u;
    }
    int pos = v - nl;                                    // exclusive offset
    int cnt = __shfl_sync(0xffffffffu, v, 31);
    if (cnt > MAXDEG) cnt = MAXDEG;

#pragma unroll
    for (int t = 0; t < 8; t++) {
        const float* vals = (const float*)&av[t];
#pragma unroll
        for (int c = 0; c < 4; c++) {
            if ((m >> (t * 4 + c)) & 1u) {
                if (pos < MAXDEG) {
                    sh_j[w][pos] = t * 128 + lane * 4 + c;
                    sh_a[w][pos] = vals[c];
                }
                pos++;
            }
        }
    }
    __syncwarp();

    // ---- phase A: one neighbor per lane, all-scalar pair math ----
    float beta_part = 0.0f;
    for (int k = lane; k < cnt; k += 32) {
        int j = sh_j[w][k];
        float aj = sh_a[w][k];
        const float4* q4 = (const float4*)(x + (size_t)j * DD);
        float d = 0.0f, y2j = 0.0f, qw = 0.0f;
#pragma unroll
        for (int t = 0; t < DD / 4; t++) {
            float4 qq = q4[t];
            float4 pq = sh_p[w][t];
            float4 wr = sh_Wr[t];
            d   = fmaf(pq.x, qq.x, d);   d   = fmaf(pq.y, qq.y, d);
            d   = fmaf(pq.z, qq.z, d);   d   = fmaf(pq.w, qq.w, d);
            y2j = fmaf(qq.x, qq.x, y2j); y2j = fmaf(qq.y, qq.y, y2j);
            y2j = fmaf(qq.z, qq.z, y2j); y2j = fmaf(qq.w, qq.w, y2j);
            qw  = fmaf(qq.x, wr.x, qw);  qw  = fmaf(qq.y, wr.y, qw);
            qw  = fmaf(qq.z, wr.z, qw);  qw  = fmaf(qq.w, wr.w, qw);
        }
        float pnj = fmaxf(sqrtf(y2j), MIN_NORM);
        float rightj = (artanh_clip(pnj) / pnj) * qw;    // logmap0(q).W_right

        float A   = 1.0f - 2.0f * d + y2j;
        float den = 1.0f - 2.0f * d + x2i * y2j;
        float inv_den = 1.0f / fmaxf(den, MIN_NORM);
        float num2 = fmaxf(A * A * x2i - 2.0f * A * B * d + B * B * y2j, 0.0f);
        float sn = fmaxf(sqrtf(num2) * inv_den, MIN_NORM);
        float coef = two_over_lam * artanh_clip(sn) / sn;
        float wgt  = aj / (1.0f + __expf(-(lefti + rightj)));
        float alpha = wgt * coef * inv_den;
        sh_a[w][k] = alpha;
        beta_part = fmaf(alpha, A, beta_part);
    }
    float beta = warp_sum(beta_part);
    __syncwarp();

    // ---- phase B: acc = B * sum(alpha_j q_j) - beta * p ----
    float acc0 = 0.0f, acc1 = 0.0f;
    for (int k = 0; k < cnt; k++) {
        float al = sh_a[w][k];
        const float* q = x + (size_t)sh_j[w][k] * DD;
        acc0 = fmaf(al, q[lane],      acc0);
        acc1 = fmaf(al, q[lane + 32], acc1);
    }
    acc0 = B * acc0 - beta * p0;
    acc1 = B * acc1 - beta * p1;

    // ---- epilogue: reference does _expmap(u = x_i, p = support_t) ----
    float s2 = warp_sum(acc0 * acc0 + acc1 * acc1);      // |support|^2
    float un = fmaxf(sqrtf(x2i), MIN_NORM);              // |u| = |x_i|
    float tol = fmaxf(1.0f - s2, MIN_NORM);
    float sc = tanhf(un / tol) / un;
    float s0 = sc * p0, s1 = sc * p1;                    // "second"
    float y2 = sc * sc * x2i;

    float xy = warp_sum(acc0 * s0 + acc1 * s1);
    float numc = 1.0f + 2.0f * xy + y2;
    float den  = fmaxf(1.0f + 2.0f * xy + s2 * y2, MIN_NORM);
    float inv_den = 1.0f / den;
    float r0 = (numc * acc0 + (1.0f - s2) * s0) * inv_den;
    float r1 = (numc * acc1 + (1.0f - s2) * s1) * inv_den;

    float n = fmaxf(sqrtf(warp_sum(r0 * r0 + r1 * r1)), MIN_NORM);
    float maxnorm = 1.0f - PROJ_EPS;
    if (n > maxnorm) {
        float s = maxnorm / n;
        r0 *= s; r1 *= s;
    }
    out[i * DD + lane]      = r0;
    out[i * DD + lane + 32] = r1;
}

extern "C" void kernel_launch(void* const* d_in, const int* in_sizes, int n_in,
                              void* d_out, int out_size) {
    const float* x = nullptr; const float* adj = nullptr;
    const float* att_W = nullptr; const float* att_b = nullptr;
    for (int k = 0; k < n_in; k++) {
        int sz = in_sizes[k];
        if (sz == NN * NN)      adj   = (const float*)d_in[k];
        else if (sz == NN * DD) x     = (const float*)d_in[k];
        else if (sz == 2 * DD)  att_W = (const float*)d_in[k];
        else if (sz == 1)       att_b = (const float*)d_in[k];
    }
    float* out = (float*)d_out;

    hyp_all<<<NN / WPB, WPB * 32>>>(x, adj, att_W, att_b, out);
}